// round 10
// baseline (speedup 1.0000x reference)
#include <cuda_runtime.h>
#include <cuda_bf16.h>
#include <cstdint>

__device__ double             g_total = 0.0;
__device__ unsigned long long g_rows  = 0ull;
__device__ unsigned int       g_done  = 0u;

#define THREADS      256
#define BLOCKS       888          // 148 SMs * 6
#define SLOTS        2
#define STAGE_CHUNKS (SLOTS * THREADS)   // 512 float4-chunks per stage (= 4 rows)

// Packed f32x2 FMA (sm_103a FFMA2 — PTX-only).
__device__ __forceinline__ unsigned long long fma2(unsigned long long a,
                                                   unsigned long long b,
                                                   unsigned long long c)
{
    unsigned long long d;
    asm("fma.rn.f32x2 %0, %1, %2, %3;" : "=l"(d) : "l"(a), "l"(b), "l"(c));
    return d;
}

__device__ __forceinline__ float unpack_sum(unsigned long long v)
{
    return __int_as_float((int)(v & 0xFFFFFFFFull)) +
           __int_as_float((int)(v >> 32));
}

__device__ __forceinline__ void cp16(uint32_t smem_addr, const void* gptr)
{
    asm volatile("cp.async.cg.shared.global [%0], [%1], 16;"
                 :: "r"(smem_addr), "l"(gptr));
}

__global__ __launch_bounds__(THREADS, 6)
void fused_mse_kernel(const float* __restrict__ emb,
                      const float* __restrict__ cen,
                      const int*   __restrict__ labels,
                      const int*   __restrict__ num_old_p,
                      int batch, int rows_per_block,
                      float* __restrict__ out)
{
    const int num_old = *num_old_p;

    __shared__ float4       s_e[2][STAGE_CHUNKS];
    __shared__ float4       s_c[2][STAGE_CHUNKS];
    __shared__ unsigned int s_list[128];   // packed: row | (label<<16); M <= 74
    __shared__ unsigned int s_cnt;
    __shared__ unsigned int s_warpbase[THREADS / 32];
    __shared__ double       s_total;

    if (threadIdx.x == 0) { s_cnt = 0u; s_total = 0.0; }
    __syncthreads();

    // ---- Per-block compaction of this block's row slice ----
    const int row0  = blockIdx.x * rows_per_block;
    int nrows = batch - row0;
    if (nrows > rows_per_block) nrows = rows_per_block;
    if (nrows < 0) nrows = 0;

    {
        const int  tid    = threadIdx.x;
        const int  lane   = tid & 31;
        const int  wid    = tid >> 5;
        bool       active = false;
        int        label  = 0;
        const int  row    = row0 + tid;
        if (tid < nrows) { label = labels[row]; active = (label < num_old); }
        const unsigned mask = __ballot_sync(0xFFFFFFFFu, active);
        if (lane == 0) s_warpbase[wid] = atomicAdd(&s_cnt, (unsigned)__popc(mask));
        __syncwarp();
        if (active) {
            const unsigned pos = s_warpbase[wid] + (unsigned)__popc(mask & ((1u << lane) - 1u));
            s_list[pos] = (unsigned)row | ((unsigned)label << 16);
        }
    }
    __syncthreads();

    const unsigned M  = s_cnt;          // active rows in this block
    const unsigned Mc = M * 128u;       // float4 chunks (128 per row)

    const float4* __restrict__ emb4 = reinterpret_cast<const float4*>(emb);
    const float4* __restrict__ cen4 = reinterpret_cast<const float4*>(cen);

    const unsigned long long NEG1 = 0xBF800000BF800000ull;   // (-1.0f, -1.0f)
    unsigned long long accA = 0ull, accB = 0ull, accC = 0ull, accD = 0ull;

    const unsigned tid        = threadIdx.x;
    const unsigned full       = Mc / STAGE_CHUNKS;     // fully-populated stages
    const uint32_t sm_e_base  = (uint32_t)__cvta_generic_to_shared(&s_e[0][0]);
    const uint32_t sm_c_base  = (uint32_t)__cvta_generic_to_shared(&s_c[0][0]);

    // Issue one stage's async copies (this thread's SLOTS chunks).
    auto issue_stage = [&](unsigned k, unsigned buf) {
        const unsigned base = k * STAGE_CHUNKS;
        #pragma unroll
        for (int s = 0; s < SLOTS; s++) {
            const unsigned j   = base + (unsigned)s * THREADS + tid;
            const unsigned p   = s_list[j >> 7];
            const unsigned off = j & 127u;
            const unsigned sl  = (unsigned)s * THREADS + tid;
            cp16(sm_e_base + (buf * STAGE_CHUNKS + sl) * 16u,
                 emb4 + ((p & 0xFFFFu) * 128u + off));
            cp16(sm_c_base + (buf * STAGE_CHUNKS + sl) * 16u,
                 cen4 + ((p >> 16) * 128u + off));
        }
        asm volatile("cp.async.commit_group;");
    };

    // ---- Pipelined main loop (no __syncthreads: each thread consumes
    //      exactly the chunks it issued) ----
    unsigned buf = 0u;
    if (full > 0u) issue_stage(0u, 0u);
    for (unsigned k = 0; k < full; k++) {
        if (k + 1u < full) {
            issue_stage(k + 1u, buf ^ 1u);
            asm volatile("cp.async.wait_group 1;");
        } else {
            asm volatile("cp.async.wait_group 0;");
        }
        #pragma unroll
        for (int s = 0; s < SLOTS; s++) {
            const unsigned sl = (unsigned)s * THREADS + tid;
            const float4 ev = s_e[buf][sl];
            const float4 cv = s_c[buf][sl];
            const unsigned long long exy = ((unsigned long long)__float_as_uint(ev.y) << 32) | __float_as_uint(ev.x);
            const unsigned long long ezw = ((unsigned long long)__float_as_uint(ev.w) << 32) | __float_as_uint(ev.z);
            const unsigned long long cxy = ((unsigned long long)__float_as_uint(cv.y) << 32) | __float_as_uint(cv.x);
            const unsigned long long czw = ((unsigned long long)__float_as_uint(cv.w) << 32) | __float_as_uint(cv.z);
            unsigned long long d;
            d = fma2(cxy, NEG1, exy); accA = fma2(d, d, accA);
            d = fma2(czw, NEG1, ezw); accB = fma2(d, d, accB);
        }
        buf ^= 1u;
    }

    // ---- Remainder: < STAGE_CHUNKS chunks, guarded direct loads ----
    for (unsigned i = full * STAGE_CHUNKS + tid; i < Mc; i += THREADS) {
        const unsigned p  = s_list[i >> 7];
        const float4   ev = __ldcs(emb4 + ((p & 0xFFFFu) * 128u + (i & 127u)));
        const float4   cv = cen4[(p >> 16) * 128u + (i & 127u)];
        const unsigned long long exy = ((unsigned long long)__float_as_uint(ev.y) << 32) | __float_as_uint(ev.x);
        const unsigned long long ezw = ((unsigned long long)__float_as_uint(ev.w) << 32) | __float_as_uint(ev.z);
        const unsigned long long cxy = ((unsigned long long)__float_as_uint(cv.y) << 32) | __float_as_uint(cv.x);
        const unsigned long long czw = ((unsigned long long)__float_as_uint(cv.w) << 32) | __float_as_uint(cv.z);
        unsigned long long d;
        d = fma2(cxy, NEG1, exy); accC = fma2(d, d, accC);
        d = fma2(czw, NEG1, ezw); accD = fma2(d, d, accD);
    }

    // ---- Reduction ----
    float acc = unpack_sum(accA) + unpack_sum(accB) +
                unpack_sum(accC) + unpack_sum(accD);
    #pragma unroll
    for (int off = 16; off > 0; off >>= 1)
        acc += __shfl_xor_sync(0xFFFFFFFFu, acc, off);

    if ((threadIdx.x & 31) == 0 && acc != 0.0f)
        atomicAdd(&s_total, (double)acc);
    __syncthreads();

    if (threadIdx.x == 0) {
        if (s_total != 0.0) atomicAdd(&g_total, s_total);
        if (M != 0u)        atomicAdd(&g_rows, (unsigned long long)M);
        __threadfence();
        const unsigned ticket = atomicAdd(&g_done, 1u);
        if (ticket == gridDim.x - 1u) {
            const double             t = g_total * (1.0 / 512.0);
            const unsigned long long c = g_rows;
            out[0] = (c == 0ull) ? (float)t : (float)(t / (double)c);
            g_total = 0.0;
            g_rows  = 0ull;
            g_done  = 0u;
        }
    }
}

extern "C" void kernel_launch(void* const* d_in, const int* in_sizes, int n_in,
                              void* d_out, int out_size)
{
    const float* emb       = (const float*)d_in[0];
    const float* cen       = (const float*)d_in[1];
    const int*   labels    = (const int*)d_in[2];
    const int*   num_old_p = (const int*)d_in[3];
    float*       out       = (float*)d_out;

    const int dim   = 512;
    const int batch = in_sizes[0] / dim;                        // 65536
    const int rows_per_block = (batch + BLOCKS - 1) / BLOCKS;   // 74

    fused_mse_kernel<<<BLOCKS, THREADS>>>(emb, cen, labels, num_old_p,
                                          batch, rows_per_block, out);
}

// round 11
// speedup vs baseline: 1.2584x; 1.2584x over previous
#include <cuda_runtime.h>
#include <cuda_bf16.h>
#include <cstdint>

__device__ double             g_total = 0.0;
__device__ unsigned long long g_rows  = 0ull;
__device__ unsigned int       g_done  = 0u;

#define THREADS 256
#define BLOCKS  888   // 148 SMs * 6

// Packed f32x2 FMA (sm_103a FFMA2 — PTX-only).
__device__ __forceinline__ unsigned long long fma2(unsigned long long a,
                                                   unsigned long long b,
                                                   unsigned long long c)
{
    unsigned long long d;
    asm("fma.rn.f32x2 %0, %1, %2, %3;" : "=l"(d) : "l"(a), "l"(b), "l"(c));
    return d;
}

__device__ __forceinline__ float unpack_sum(unsigned long long v)
{
    return __int_as_float((int)(v & 0xFFFFFFFFull)) +
           __int_as_float((int)(v >> 32));
}

__global__ __launch_bounds__(THREADS, 6)
void fused_mse_kernel(const float* __restrict__ emb,
                      const float* __restrict__ cen,
                      const int*   __restrict__ labels,
                      const int*   __restrict__ num_old_p,
                      int batch, int rows_per_block,
                      float* __restrict__ out)
{
    const int num_old = *num_old_p;

    __shared__ unsigned int s_list[128];   // packed: row | (label<<16); M <= 74
    __shared__ unsigned int s_cnt;
    __shared__ unsigned int s_warpbase[THREADS / 32];
    __shared__ double       s_total;

    if (threadIdx.x == 0) { s_cnt = 0u; s_total = 0.0; }
    __syncthreads();

    // ---- Per-block compaction of this block's row slice ----
    const int row0  = blockIdx.x * rows_per_block;
    int nrows = batch - row0;
    if (nrows > rows_per_block) nrows = rows_per_block;
    if (nrows < 0) nrows = 0;

    {
        const int  tid    = threadIdx.x;
        const int  lane   = tid & 31;
        const int  wid    = tid >> 5;
        bool       active = false;
        int        label  = 0;
        const int  row    = row0 + tid;
        if (tid < nrows) { label = labels[row]; active = (label < num_old); }
        const unsigned mask = __ballot_sync(0xFFFFFFFFu, active);
        if (lane == 0) s_warpbase[wid] = atomicAdd(&s_cnt, (unsigned)__popc(mask));
        __syncwarp();
        if (active) {
            const unsigned pos = s_warpbase[wid] + (unsigned)__popc(mask & ((1u << lane) - 1u));
            s_list[pos] = (unsigned)row | ((unsigned)label << 16);
        }
    }
    __syncthreads();

    const unsigned M  = s_cnt;          // active rows in this block
    const unsigned Mc = M * 128u;       // double2 chunks (128 per row)

    const double2* __restrict__ emb2 = reinterpret_cast<const double2*>(emb);
    const double2* __restrict__ cen2 = reinterpret_cast<const double2*>(cen);

    const unsigned long long NEG1 = 0xBF800000BF800000ull;   // (-1.0f, -1.0f)
    unsigned long long accA = 0ull, accB = 0ull, accC = 0ull, accD = 0ull;

    unsigned i = threadIdx.x;

    // ---- Steady state: no guards, 8 loads batched before consumption.
    //      Plain cached loads: the ~66 MB working set fits in L2 (126 MB)
    //      and persists across graph replays — do NOT mark evict-first. ----
    for (; i + 3u * THREADS < Mc; i += 4u * THREADS) {
        const unsigned j0 = i;
        const unsigned j1 = i + THREADS;
        const unsigned j2 = i + 2u * THREADS;
        const unsigned j3 = i + 3u * THREADS;

        const unsigned p0 = s_list[j0 >> 7];
        const unsigned p1 = s_list[j1 >> 7];
        const unsigned p2 = s_list[j2 >> 7];
        const unsigned p3 = s_list[j3 >> 7];

        const unsigned e_i0 = (p0 & 0xFFFFu) * 128u + (j0 & 127u);
        const unsigned c_i0 = (p0 >> 16)     * 128u + (j0 & 127u);
        const unsigned e_i1 = (p1 & 0xFFFFu) * 128u + (j1 & 127u);
        const unsigned c_i1 = (p1 >> 16)     * 128u + (j1 & 127u);
        const unsigned e_i2 = (p2 & 0xFFFFu) * 128u + (j2 & 127u);
        const unsigned c_i2 = (p2 >> 16)     * 128u + (j2 & 127u);
        const unsigned e_i3 = (p3 & 0xFFFFu) * 128u + (j3 & 127u);
        const unsigned c_i3 = (p3 >> 16)     * 128u + (j3 & 127u);

        const double2 e0 = __ldg(emb2 + e_i0);
        const double2 c0 = __ldg(cen2 + c_i0);
        const double2 e1 = __ldg(emb2 + e_i1);
        const double2 c1 = __ldg(cen2 + c_i1);
        const double2 e2 = __ldg(emb2 + e_i2);
        const double2 c2 = __ldg(cen2 + c_i2);
        const double2 e3 = __ldg(emb2 + e_i3);
        const double2 c3 = __ldg(cen2 + c_i3);

        unsigned long long d;
        d = fma2(__double_as_longlong(c0.x), NEG1, __double_as_longlong(e0.x)); accA = fma2(d, d, accA);
        d = fma2(__double_as_longlong(c0.y), NEG1, __double_as_longlong(e0.y)); accB = fma2(d, d, accB);
        d = fma2(__double_as_longlong(c1.x), NEG1, __double_as_longlong(e1.x)); accC = fma2(d, d, accC);
        d = fma2(__double_as_longlong(c1.y), NEG1, __double_as_longlong(e1.y)); accD = fma2(d, d, accD);
        d = fma2(__double_as_longlong(c2.x), NEG1, __double_as_longlong(e2.x)); accA = fma2(d, d, accA);
        d = fma2(__double_as_longlong(c2.y), NEG1, __double_as_longlong(e2.y)); accB = fma2(d, d, accB);
        d = fma2(__double_as_longlong(c3.x), NEG1, __double_as_longlong(e3.x)); accC = fma2(d, d, accC);
        d = fma2(__double_as_longlong(c3.y), NEG1, __double_as_longlong(e3.y)); accD = fma2(d, d, accD);
    }

    // ---- Remainder: <= 4 guarded strided iterations ----
    for (; i < Mc; i += THREADS) {
        const unsigned p  = s_list[i >> 7];
        const double2  ev = __ldg(emb2 + ((p & 0xFFFFu) * 128u + (i & 127u)));
        const double2  cv = __ldg(cen2 + ((p >> 16) * 128u + (i & 127u)));
        unsigned long long d;
        d = fma2(__double_as_longlong(cv.x), NEG1, __double_as_longlong(ev.x)); accA = fma2(d, d, accA);
        d = fma2(__double_as_longlong(cv.y), NEG1, __double_as_longlong(ev.y)); accB = fma2(d, d, accB);
    }

    // ---- Reduction ----
    float acc = unpack_sum(accA) + unpack_sum(accB) +
                unpack_sum(accC) + unpack_sum(accD);
    #pragma unroll
    for (int off = 16; off > 0; off >>= 1)
        acc += __shfl_xor_sync(0xFFFFFFFFu, acc, off);

    if ((threadIdx.x & 31) == 0 && acc != 0.0f)
        atomicAdd(&s_total, (double)acc);
    __syncthreads();

    if (threadIdx.x == 0) {
        if (s_total != 0.0) atomicAdd(&g_total, s_total);
        if (M != 0u)        atomicAdd(&g_rows, (unsigned long long)M);
        __threadfence();
        const unsigned ticket = atomicAdd(&g_done, 1u);
        if (ticket == gridDim.x - 1u) {
            const double             t = g_total * (1.0 / 512.0);
            const unsigned long long c = g_rows;
            out[0] = (c == 0ull) ? (float)t : (float)(t / (double)c);
            g_total = 0.0;
            g_rows  = 0ull;
            g_done  = 0u;
        }
    }
}

extern "C" void kernel_launch(void* const* d_in, const int* in_sizes, int n_in,
                              void* d_out, int out_size)
{
    const float* emb       = (const float*)d_in[0];
    const float* cen       = (const float*)d_in[1];
    const int*   labels    = (const int*)d_in[2];
    const int*   num_old_p = (const int*)d_in[3];
    float*       out       = (float*)d_out;

    const int dim   = 512;
    const int batch = in_sizes[0] / dim;                        // 65536
    const int rows_per_block = (batch + BLOCKS - 1) / BLOCKS;   // 74

    fused_mse_kernel<<<BLOCKS, THREADS>>>(emb, cen, labels, num_old_p,
                                          batch, rows_per_block, out);
}